// round 12
// baseline (speedup 1.0000x reference)
#include <cuda_runtime.h>

// RCNNTargetGenerator — compute per-thread, stores via smem + cp.async.bulk
// (TMA 1D bulk store): each CTA emits three 4KB contiguous write bursts
// instead of interleaved per-warp STG streams. Loads stay scalar __ldcs.
// (Resubmission: R11 failed on broker infra, not the kernel.)
//
// Inputs (metadata order):
//   d_in[0] gt_rois  float32 [1,N,5]  (x1,y1,x2,y2,cls)
//   d_in[1] rois     float32 [1,N,5]  (batch, x1,y1,x2,y2)
//   d_in[2] labels   int32   [N]
//   d_in[3] means    float32 [4]
//   d_in[4] stds     float32 [4]
//   d_in[5] inside_w float32 [4]
// Output: float32 [3, N, 4]: targets | inside_w | outside_w

__device__ __forceinline__ unsigned smem_u32(const void* p)
{
    unsigned a;
    asm("{ .reg .u64 t; cvta.to.shared.u64 t, %1; cvt.u32.u64 %0, t; }"
        : "=r"(a) : "l"(p));
    return a;
}

__global__ __launch_bounds__(256) void rcnn_target_tma(
    const float* __restrict__ gt,      // [N,5]
    const float* __restrict__ rois,    // [N,5]
    const int*   __restrict__ labels,  // [N]
    const float* __restrict__ means,
    const float* __restrict__ stds,
    const float* __restrict__ iw,
    float* __restrict__ out_t,         // [N*4]
    float* __restrict__ out_in,
    float* __restrict__ out_out,
    int n)
{
    __shared__ __align__(128) float4 sT[256];
    __shared__ __align__(128) float4 sI[256];
    __shared__ __align__(128) float4 sO[256];

    int base = blockIdx.x * 256;
    int i = base + threadIdx.x;

    float4 z4 = make_float4(0.0f, 0.0f, 0.0f, 0.0f);
    float4 t4 = z4, i4 = z4, o4 = z4;

    if (i < n) {
        // broadcast constants (L1-resident)
        float m0 = __ldg(means + 0), m1 = __ldg(means + 1),
              m2 = __ldg(means + 2), m3 = __ldg(means + 3);
        float is0 = __fdividef(1.0f, __ldg(stds + 0));
        float is1 = __fdividef(1.0f, __ldg(stds + 1));
        float is2 = __fdividef(1.0f, __ldg(stds + 2));
        float is3 = __fdividef(1.0f, __ldg(stds + 3));
        float w0 = __ldg(iw + 0), w1 = __ldg(iw + 1),
              w2 = __ldg(iw + 2), w3 = __ldg(iw + 3);

        const float* r = rois + (size_t)i * 5;
        float ex_x1 = __ldcs(r + 1);
        float ex_y1 = __ldcs(r + 2);
        float ex_x2 = __ldcs(r + 3);
        float ex_y2 = __ldcs(r + 4);

        const float* g = gt + (size_t)i * 5;
        float gt_x1 = __ldcs(g + 0);
        float gt_y1 = __ldcs(g + 1);
        float gt_x2 = __ldcs(g + 2);
        float gt_y2 = __ldcs(g + 3);

        bool pos = __ldcs(labels + i) > 0;

        float ex_w  = ex_x2 - ex_x1 + 1.0f;
        float ex_h  = ex_y2 - ex_y1 + 1.0f;
        float ex_cx = ex_x1 + 0.5f * ex_w;
        float ex_cy = ex_y1 + 0.5f * ex_h;
        float gt_w  = gt_x2 - gt_x1 + 1.0f;
        float gt_h  = gt_y2 - gt_y1 + 1.0f;
        float gt_cx = gt_x1 + 0.5f * gt_w;
        float gt_cy = gt_y1 + 0.5f * gt_h;

        float dx = __fdividef(gt_cx - ex_cx, ex_w);
        float dy = __fdividef(gt_cy - ex_cy, ex_h);
        float dw = __logf(__fdividef(gt_w, ex_w));
        float dh = __logf(__fdividef(gt_h, ex_h));

        dx = (dx - m0) * is0;
        dy = (dy - m1) * is1;
        dw = (dw - m2) * is2;
        dh = (dh - m3) * is3;

        if (pos) {
            t4 = make_float4(dx, dy, dw, dh);
            i4 = make_float4(w0, w1, w2, w3);
            o4 = make_float4(w0 > 0.0f ? 1.0f : 0.0f,
                             w1 > 0.0f ? 1.0f : 0.0f,
                             w2 > 0.0f ? 1.0f : 0.0f,
                             w3 > 0.0f ? 1.0f : 0.0f);
        }
    }

    // stage in smem (STS.128, conflict-free: 512B per warp per tensor)
    sT[threadIdx.x] = t4;
    sI[threadIdx.x] = i4;
    sO[threadIdx.x] = o4;
    __syncthreads();

    // one thread per CTA fires three bulk store bursts (4KB each, contiguous)
    if (threadIdx.x == 0) {
        int rows  = n - base;
        if (rows > 256) rows = 256;
        unsigned bytes = (unsigned)rows * 16u;

        unsigned aT = smem_u32(sT);
        unsigned aI = smem_u32(sI);
        unsigned aO = smem_u32(sO);
        float* dT = out_t   + (size_t)base * 4;
        float* dI = out_in  + (size_t)base * 4;
        float* dO = out_out + (size_t)base * 4;

        asm volatile("fence.proxy.async.shared::cta;" ::: "memory");
        asm volatile("cp.async.bulk.global.shared::cta.bulk_group [%0], [%1], %2;"
                     :: "l"(dT), "r"(aT), "r"(bytes) : "memory");
        asm volatile("cp.async.bulk.global.shared::cta.bulk_group [%0], [%1], %2;"
                     :: "l"(dI), "r"(aI), "r"(bytes) : "memory");
        asm volatile("cp.async.bulk.global.shared::cta.bulk_group [%0], [%1], %2;"
                     :: "l"(dO), "r"(aO), "r"(bytes) : "memory");
        asm volatile("cp.async.bulk.commit_group;" ::: "memory");
        asm volatile("cp.async.bulk.wait_group 0;" ::: "memory");
    }
}

extern "C" void kernel_launch(void* const* d_in, const int* in_sizes, int n_in,
                              void* d_out, int out_size)
{
    const float* gt     = (const float*)d_in[0];
    const float* rois   = (const float*)d_in[1];
    const int*   labels = (const int*)d_in[2];
    const float* means  = (const float*)d_in[3];
    const float* stds   = (const float*)d_in[4];
    const float* iw     = (const float*)d_in[5];

    int n = in_sizes[0] / 5;      // gt_rois is [1,N,5]

    float* out = (float*)d_out;
    float* out_t   = out;
    float* out_in  = out + (size_t)n * 4;
    float* out_out = out + (size_t)n * 8;

    int blocks = (n + 255) / 256;
    rcnn_target_tma<<<blocks, 256>>>(gt, rois, labels, means, stds, iw,
                                     out_t, out_in, out_out, n);
}

// round 13
// speedup vs baseline: 1.0624x; 1.0624x over previous
#include <cuda_runtime.h>

// RCNNTargetGenerator — persistent single-wave grid-stride kernel.
// grid = 148 SMs x 8 blocks = 1184 CTAs of 256 threads (one wave on B200);
// each thread processes ~6.6 rows. Eliminates the 6.6-wave structure
// (5-6 wave transitions + tail underfill) of the 7813-block launches.
// Body = R2 shape: scalar __ldcs stride-5 loads (best measured), contiguous
// float4 stores per row.
//
// Inputs (metadata order):
//   d_in[0] gt_rois  float32 [1,N,5]  (x1,y1,x2,y2,cls)
//   d_in[1] rois     float32 [1,N,5]  (batch, x1,y1,x2,y2)
//   d_in[2] labels   int32   [N]
//   d_in[3] means    float32 [4]
//   d_in[4] stds     float32 [4]
//   d_in[5] inside_w float32 [4]
// Output: float32 [3, N, 4]: targets | inside_w | outside_w

#define GRID_BLOCKS 1184   // 148 SMs * 8 resident CTAs
#define BLOCK_THREADS 256

__global__ __launch_bounds__(BLOCK_THREADS) void rcnn_target_persistent(
    const float* __restrict__ gt,      // [N,5]
    const float* __restrict__ rois,    // [N,5]
    const int*   __restrict__ labels,  // [N]
    const float* __restrict__ means,
    const float* __restrict__ stds,
    const float* __restrict__ iw,
    float4* __restrict__ out_t,        // [N]
    float4* __restrict__ out_in,
    float4* __restrict__ out_out,
    int n)
{
    // broadcast constants once per thread (L1-resident)
    float m0 = __ldg(means + 0), m1 = __ldg(means + 1),
          m2 = __ldg(means + 2), m3 = __ldg(means + 3);
    float is0 = __fdividef(1.0f, __ldg(stds + 0));
    float is1 = __fdividef(1.0f, __ldg(stds + 1));
    float is2 = __fdividef(1.0f, __ldg(stds + 2));
    float is3 = __fdividef(1.0f, __ldg(stds + 3));
    float w0 = __ldg(iw + 0), w1 = __ldg(iw + 1),
          w2 = __ldg(iw + 2), w3 = __ldg(iw + 3);

    float4 iw4 = make_float4(w0, w1, w2, w3);
    float4 ow4 = make_float4(w0 > 0.0f ? 1.0f : 0.0f,
                             w1 > 0.0f ? 1.0f : 0.0f,
                             w2 > 0.0f ? 1.0f : 0.0f,
                             w3 > 0.0f ? 1.0f : 0.0f);
    float4 z4 = make_float4(0.0f, 0.0f, 0.0f, 0.0f);

    int stride = GRID_BLOCKS * BLOCK_THREADS;

#pragma unroll 2
    for (int i = blockIdx.x * BLOCK_THREADS + threadIdx.x; i < n; i += stride) {
        const float* r = rois + (size_t)i * 5;
        float ex_x1 = __ldcs(r + 1);
        float ex_y1 = __ldcs(r + 2);
        float ex_x2 = __ldcs(r + 3);
        float ex_y2 = __ldcs(r + 4);

        const float* g = gt + (size_t)i * 5;
        float gt_x1 = __ldcs(g + 0);
        float gt_y1 = __ldcs(g + 1);
        float gt_x2 = __ldcs(g + 2);
        float gt_y2 = __ldcs(g + 3);

        bool pos = __ldcs(labels + i) > 0;

        float ex_w  = ex_x2 - ex_x1 + 1.0f;
        float ex_h  = ex_y2 - ex_y1 + 1.0f;
        float ex_cx = ex_x1 + 0.5f * ex_w;
        float ex_cy = ex_y1 + 0.5f * ex_h;
        float gt_w  = gt_x2 - gt_x1 + 1.0f;
        float gt_h  = gt_y2 - gt_y1 + 1.0f;
        float gt_cx = gt_x1 + 0.5f * gt_w;
        float gt_cy = gt_y1 + 0.5f * gt_h;

        float dx = __fdividef(gt_cx - ex_cx, ex_w);
        float dy = __fdividef(gt_cy - ex_cy, ex_h);
        float dw = __logf(__fdividef(gt_w, ex_w));
        float dh = __logf(__fdividef(gt_h, ex_h));

        dx = (dx - m0) * is0;
        dy = (dy - m1) * is1;
        dw = (dw - m2) * is2;
        dh = (dh - m3) * is3;

        float4 t4 = z4, i4 = z4, o4 = z4;
        if (pos) {
            t4 = make_float4(dx, dy, dw, dh);
            i4 = iw4;
            o4 = ow4;
        }

        out_t[i]   = t4;   // warp: 512B contiguous per tensor
        out_in[i]  = i4;
        out_out[i] = o4;
    }
}

extern "C" void kernel_launch(void* const* d_in, const int* in_sizes, int n_in,
                              void* d_out, int out_size)
{
    const float* gt     = (const float*)d_in[0];
    const float* rois   = (const float*)d_in[1];
    const int*   labels = (const int*)d_in[2];
    const float* means  = (const float*)d_in[3];
    const float* stds   = (const float*)d_in[4];
    const float* iw     = (const float*)d_in[5];

    int n = in_sizes[0] / 5;      // gt_rois is [1,N,5]

    float* out = (float*)d_out;
    float4* out_t   = (float4*)out;
    float4* out_in  = (float4*)(out + (size_t)n * 4);
    float4* out_out = (float4*)(out + (size_t)n * 8);

    rcnn_target_persistent<<<GRID_BLOCKS, BLOCK_THREADS>>>(
        gt, rois, labels, means, stds, iw, out_t, out_in, out_out, n);
}

// round 14
// speedup vs baseline: 1.2303x; 1.1580x over previous
#include <cuda_runtime.h>

// RCNNTargetGenerator — FINAL: R5 smem-staged coalesced loads (best measured
// dur_us) + __stcs streaming stores (st.global.cs: streaming in L1+L2, eager
// writeback drain). All other mechanism classes probed and flat/regressed:
// issue shape, vector width, L2 createpolicy (both directions), TMA bulk
// stores, persistent grid. Compulsory traffic 184 MB/replay at ~5.5 TB/s
// effective mixed-stream BW puts the practical roofline at ~33.4 us.
//
// Inputs (metadata order):
//   d_in[0] gt_rois  float32 [1,N,5]  (x1,y1,x2,y2,cls)
//   d_in[1] rois     float32 [1,N,5]  (batch, x1,y1,x2,y2)
//   d_in[2] labels   int32   [N]
//   d_in[3] means    float32 [4]
//   d_in[4] stds     float32 [4]
//   d_in[5] inside_w float32 [4]
// Output: float32 [3, N, 4]: targets | inside_w | outside_w

#define ROWS_PER_BLOCK 256
#define F4_PER_BLOCK   (ROWS_PER_BLOCK * 5 / 4)   // 320

__global__ __launch_bounds__(256) void rcnn_target_final(
    const float4* __restrict__ gt4,
    const float4* __restrict__ rois4,
    const int*    __restrict__ labels,
    const float*  __restrict__ means,
    const float*  __restrict__ stds,
    const float*  __restrict__ iw,
    float4* __restrict__ out_t,
    float4* __restrict__ out_in,
    float4* __restrict__ out_out,
    int n)                                // N rows
{
    __shared__ float4 sR[F4_PER_BLOCK];
    __shared__ float4 sG[F4_PER_BLOCK];

    int rowBase = blockIdx.x * ROWS_PER_BLOCK;
    size_t f4Base = (size_t)blockIdx.x * F4_PER_BLOCK;
    size_t f4Total = ((size_t)n * 5) / 4;

    // cooperative fully-coalesced load of this block's 256 rows
#pragma unroll
    for (int k = threadIdx.x; k < F4_PER_BLOCK; k += 256) {
        size_t gidx = f4Base + k;
        if (gidx < f4Total) {
            sR[k] = __ldcs(rois4 + gidx);
            sG[k] = __ldcs(gt4 + gidx);
        }
    }
    __syncthreads();

    int i = rowBase + threadIdx.x;
    if (i >= n) return;

    const float* rf = reinterpret_cast<const float*>(sR);
    const float* gf = reinterpret_cast<const float*>(sG);
    int r5 = threadIdx.x * 5;   // 5*tid mod 32 covers all banks: conflict-free

    float ex_x1 = rf[r5 + 1];
    float ex_y1 = rf[r5 + 2];
    float ex_x2 = rf[r5 + 3];
    float ex_y2 = rf[r5 + 4];
    float gt_x1 = gf[r5 + 0];
    float gt_y1 = gf[r5 + 1];
    float gt_x2 = gf[r5 + 2];
    float gt_y2 = gf[r5 + 3];

    bool pos = __ldcs(labels + i) > 0;

    // broadcast constants (L1-resident)
    float m0 = __ldg(means + 0), m1 = __ldg(means + 1),
          m2 = __ldg(means + 2), m3 = __ldg(means + 3);
    float is0 = __fdividef(1.0f, __ldg(stds + 0));
    float is1 = __fdividef(1.0f, __ldg(stds + 1));
    float is2 = __fdividef(1.0f, __ldg(stds + 2));
    float is3 = __fdividef(1.0f, __ldg(stds + 3));
    float w0 = __ldg(iw + 0), w1 = __ldg(iw + 1),
          w2 = __ldg(iw + 2), w3 = __ldg(iw + 3);

    float ex_w  = ex_x2 - ex_x1 + 1.0f;
    float ex_h  = ex_y2 - ex_y1 + 1.0f;
    float ex_cx = ex_x1 + 0.5f * ex_w;
    float ex_cy = ex_y1 + 0.5f * ex_h;
    float gt_w  = gt_x2 - gt_x1 + 1.0f;
    float gt_h  = gt_y2 - gt_y1 + 1.0f;
    float gt_cx = gt_x1 + 0.5f * gt_w;
    float gt_cy = gt_y1 + 0.5f * gt_h;

    float dx = __fdividef(gt_cx - ex_cx, ex_w);
    float dy = __fdividef(gt_cy - ex_cy, ex_h);
    float dw = __logf(__fdividef(gt_w, ex_w));
    float dh = __logf(__fdividef(gt_h, ex_h));

    dx = (dx - m0) * is0;
    dy = (dy - m1) * is1;
    dw = (dw - m2) * is2;
    dh = (dh - m3) * is3;

    float4 z4 = make_float4(0.0f, 0.0f, 0.0f, 0.0f);
    float4 t4 = z4, i4 = z4, o4 = z4;
    if (pos) {
        t4 = make_float4(dx, dy, dw, dh);
        i4 = make_float4(w0, w1, w2, w3);
        o4 = make_float4(w0 > 0.0f ? 1.0f : 0.0f,
                         w1 > 0.0f ? 1.0f : 0.0f,
                         w2 > 0.0f ? 1.0f : 0.0f,
                         w3 > 0.0f ? 1.0f : 0.0f);
    }

    __stcs(out_t + i,   t4);   // warp: 512B contiguous per tensor, streaming
    __stcs(out_in + i,  i4);
    __stcs(out_out + i, o4);
}

extern "C" void kernel_launch(void* const* d_in, const int* in_sizes, int n_in,
                              void* d_out, int out_size)
{
    const float4* gt4   = (const float4*)d_in[0];
    const float4* rois4 = (const float4*)d_in[1];
    const int*    labels= (const int*)d_in[2];
    const float*  means = (const float*)d_in[3];
    const float*  stds  = (const float*)d_in[4];
    const float*  iw    = (const float*)d_in[5];

    int n = in_sizes[0] / 5;      // gt_rois is [1,N,5]

    float* out = (float*)d_out;
    float4* out_t   = (float4*)out;
    float4* out_in  = (float4*)(out + (size_t)n * 4);
    float4* out_out = (float4*)(out + (size_t)n * 8);

    int blocks = (n + ROWS_PER_BLOCK - 1) / ROWS_PER_BLOCK;
    rcnn_target_final<<<blocks, 256>>>(gt4, rois4, labels, means, stds, iw,
                                       out_t, out_in, out_out, n);
}

// round 15
// speedup vs baseline: 1.2326x; 1.0019x over previous
#include <cuda_runtime.h>

// RCNNTargetGenerator — warp-staged coalesced loads (no block barrier) +
// contiguous float4 __stcs streaming stores.
//
// Structure: each warp w of a 256-thread block covers rows 32w..32w+31 of its
// block's 256-row tile = float4 indices 40w..40w+39 of the [N,5] input viewed
// as float4 (N divisible by 32 -> every active warp has exactly 32 full rows).
// The staging exchange is warp-local, so __syncwarp() replaces __syncthreads():
// each warp computes as soon as its own loads land, warps fully decoupled.
//
// Inputs (metadata order):
//   d_in[0] gt_rois  float32 [1,N,5]  (x1,y1,x2,y2,cls)
//   d_in[1] rois     float32 [1,N,5]  (batch, x1,y1,x2,y2)
//   d_in[2] labels   int32   [N]
//   d_in[3] means    float32 [4]
//   d_in[4] stds     float32 [4]
//   d_in[5] inside_w float32 [4]
// Output: float32 [3, N, 4]: targets | inside_w | outside_w

#define ROWS_PER_BLOCK 256
#define F4_PER_WARP    40     // 32 rows * 5 floats / 4
#define F4_PER_BLOCK   (F4_PER_WARP * 8)   // 320

__global__ __launch_bounds__(256) void rcnn_target_warpstage(
    const float4* __restrict__ gt4,
    const float4* __restrict__ rois4,
    const int*    __restrict__ labels,
    const float*  __restrict__ means,
    const float*  __restrict__ stds,
    const float*  __restrict__ iw,
    float4* __restrict__ out_t,
    float4* __restrict__ out_in,
    float4* __restrict__ out_out,
    int n)
{
    __shared__ float4 sR[F4_PER_BLOCK];
    __shared__ float4 sG[F4_PER_BLOCK];

    int warpId = threadIdx.x >> 5;
    int lane   = threadIdx.x & 31;

    int rowBase = blockIdx.x * ROWS_PER_BLOCK;
    size_t f4Total = ((size_t)n * 5) / 4;

    // warp-private staging: warp w loads float4 indices [40w, 40w+40) of the
    // block's tile. Lane k loads 40w+k; lanes 0..7 also load 40w+32+k.
    int wbase = warpId * F4_PER_WARP;
    size_t gbase = (size_t)blockIdx.x * F4_PER_BLOCK + wbase;

    size_t g0 = gbase + lane;
    if (g0 < f4Total) {
        sR[wbase + lane] = __ldcs(rois4 + g0);
        sG[wbase + lane] = __ldcs(gt4 + g0);
    }
    if (lane < 8) {
        size_t g1 = gbase + 32 + lane;
        if (g1 < f4Total) {
            sR[wbase + 32 + lane] = __ldcs(rois4 + g1);
            sG[wbase + 32 + lane] = __ldcs(gt4 + g1);
        }
    }
    __syncwarp();

    int i = rowBase + threadIdx.x;
    if (i >= n) return;

    const float* rf = reinterpret_cast<const float*>(sR);
    const float* gf = reinterpret_cast<const float*>(sG);
    int r5 = threadIdx.x * 5;   // 5*lane mod 32 covers all banks: conflict-free

    float ex_x1 = rf[r5 + 1];
    float ex_y1 = rf[r5 + 2];
    float ex_x2 = rf[r5 + 3];
    float ex_y2 = rf[r5 + 4];
    float gt_x1 = gf[r5 + 0];
    float gt_y1 = gf[r5 + 1];
    float gt_x2 = gf[r5 + 2];
    float gt_y2 = gf[r5 + 3];

    bool pos = __ldcs(labels + i) > 0;

    // broadcast constants (L1-resident)
    float m0 = __ldg(means + 0), m1 = __ldg(means + 1),
          m2 = __ldg(means + 2), m3 = __ldg(means + 3);
    float is0 = __fdividef(1.0f, __ldg(stds + 0));
    float is1 = __fdividef(1.0f, __ldg(stds + 1));
    float is2 = __fdividef(1.0f, __ldg(stds + 2));
    float is3 = __fdividef(1.0f, __ldg(stds + 3));
    float w0 = __ldg(iw + 0), w1 = __ldg(iw + 1),
          w2 = __ldg(iw + 2), w3 = __ldg(iw + 3);

    float ex_w  = ex_x2 - ex_x1 + 1.0f;
    float ex_h  = ex_y2 - ex_y1 + 1.0f;
    float ex_cx = ex_x1 + 0.5f * ex_w;
    float ex_cy = ex_y1 + 0.5f * ex_h;
    float gt_w  = gt_x2 - gt_x1 + 1.0f;
    float gt_h  = gt_y2 - gt_y1 + 1.0f;
    float gt_cx = gt_x1 + 0.5f * gt_w;
    float gt_cy = gt_y1 + 0.5f * gt_h;

    float dx = __fdividef(gt_cx - ex_cx, ex_w);
    float dy = __fdividef(gt_cy - ex_cy, ex_h);
    float dw = __logf(__fdividef(gt_w, ex_w));
    float dh = __logf(__fdividef(gt_h, ex_h));

    dx = (dx - m0) * is0;
    dy = (dy - m1) * is1;
    dw = (dw - m2) * is2;
    dh = (dh - m3) * is3;

    float4 z4 = make_float4(0.0f, 0.0f, 0.0f, 0.0f);
    float4 t4 = z4, i4 = z4, o4 = z4;
    if (pos) {
        t4 = make_float4(dx, dy, dw, dh);
        i4 = make_float4(w0, w1, w2, w3);
        o4 = make_float4(w0 > 0.0f ? 1.0f : 0.0f,
                         w1 > 0.0f ? 1.0f : 0.0f,
                         w2 > 0.0f ? 1.0f : 0.0f,
                         w3 > 0.0f ? 1.0f : 0.0f);
    }

    __stcs(out_t + i,   t4);   // warp: 512B contiguous per tensor, streaming
    __stcs(out_in + i,  i4);
    __stcs(out_out + i, o4);
}

extern "C" void kernel_launch(void* const* d_in, const int* in_sizes, int n_in,
                              void* d_out, int out_size)
{
    const float4* gt4   = (const float4*)d_in[0];
    const float4* rois4 = (const float4*)d_in[1];
    const int*    labels= (const int*)d_in[2];
    const float*  means = (const float*)d_in[3];
    const float*  stds  = (const float*)d_in[4];
    const float*  iw    = (const float*)d_in[5];

    int n = in_sizes[0] / 5;      // gt_rois is [1,N,5]

    float* out = (float*)d_out;
    float4* out_t   = (float4*)out;
    float4* out_in  = (float4*)(out + (size_t)n * 4);
    float4* out_out = (float4*)(out + (size_t)n * 8);

    int blocks = (n + ROWS_PER_BLOCK - 1) / ROWS_PER_BLOCK;
    rcnn_target_warpstage<<<blocks, 256>>>(gt4, rois4, labels, means, stds, iw,
                                           out_t, out_in, out_out, n);
}

// round 16
// speedup vs baseline: 1.2446x; 1.0097x over previous
#include <cuda_runtime.h>

// RCNNTargetGenerator — FINAL (confirmation of R15 best, 33.15us):
// warp-staged coalesced loads (no block barrier) + contiguous __stcs stores.
// Micro-cleanups only: label load hoisted into the front LDG batch.
//
// Converged at the mixed-stream HBM roofline: 184 MB compulsory traffic
// (88 read + 96 write) at ~5.55 TB/s effective. All lever classes probed:
// issue shape, vector width, L2 createpolicy, TMA bulk stores, persistent
// grid, barrier scope — none moved the floor beyond noise.
//
// Inputs (metadata order):
//   d_in[0] gt_rois  float32 [1,N,5]  (x1,y1,x2,y2,cls)
//   d_in[1] rois     float32 [1,N,5]  (batch, x1,y1,x2,y2)
//   d_in[2] labels   int32   [N]
//   d_in[3] means    float32 [4]
//   d_in[4] stds     float32 [4]
//   d_in[5] inside_w float32 [4]
// Output: float32 [3, N, 4]: targets | inside_w | outside_w

#define ROWS_PER_BLOCK 256
#define F4_PER_WARP    40                  // 32 rows * 5 floats / 4
#define F4_PER_BLOCK   (F4_PER_WARP * 8)   // 320

__global__ __launch_bounds__(256) void rcnn_target_warpstage(
    const float4* __restrict__ gt4,
    const float4* __restrict__ rois4,
    const int*    __restrict__ labels,
    const float*  __restrict__ means,
    const float*  __restrict__ stds,
    const float*  __restrict__ iw,
    float4* __restrict__ out_t,
    float4* __restrict__ out_in,
    float4* __restrict__ out_out,
    int n)
{
    __shared__ float4 sR[F4_PER_BLOCK];
    __shared__ float4 sG[F4_PER_BLOCK];

    int warpId = threadIdx.x >> 5;
    int lane   = threadIdx.x & 31;

    int rowBase = blockIdx.x * ROWS_PER_BLOCK;
    int i = rowBase + threadIdx.x;
    size_t f4Total = ((size_t)n * 5) / 4;

    // front-batched global loads: label + warp-private input staging.
    // Warp w covers rows 32w..32w+31 = float4 indices [40w, 40w+40) of the
    // block tile. Lane k loads 40w+k; lanes 0..7 also load 40w+32+k.
    int pos_raw = (i < n) ? __ldcs(labels + i) : 0;

    int wbase = warpId * F4_PER_WARP;
    size_t gbase = (size_t)blockIdx.x * F4_PER_BLOCK + wbase;

    size_t g0 = gbase + lane;
    if (g0 < f4Total) {
        sR[wbase + lane] = __ldcs(rois4 + g0);
        sG[wbase + lane] = __ldcs(gt4 + g0);
    }
    if (lane < 8) {
        size_t g1 = gbase + 32 + lane;
        if (g1 < f4Total) {
            sR[wbase + 32 + lane] = __ldcs(rois4 + g1);
            sG[wbase + 32 + lane] = __ldcs(gt4 + g1);
        }
    }
    __syncwarp();

    if (i >= n) return;

    const float* rf = reinterpret_cast<const float*>(sR);
    const float* gf = reinterpret_cast<const float*>(sG);
    int r5 = threadIdx.x * 5;   // 5*lane mod 32 covers all banks: conflict-free

    float ex_x1 = rf[r5 + 1];
    float ex_y1 = rf[r5 + 2];
    float ex_x2 = rf[r5 + 3];
    float ex_y2 = rf[r5 + 4];
    float gt_x1 = gf[r5 + 0];
    float gt_y1 = gf[r5 + 1];
    float gt_x2 = gf[r5 + 2];
    float gt_y2 = gf[r5 + 3];

    // broadcast constants (L1-resident)
    float m0 = __ldg(means + 0), m1 = __ldg(means + 1),
          m2 = __ldg(means + 2), m3 = __ldg(means + 3);
    float is0 = __fdividef(1.0f, __ldg(stds + 0));
    float is1 = __fdividef(1.0f, __ldg(stds + 1));
    float is2 = __fdividef(1.0f, __ldg(stds + 2));
    float is3 = __fdividef(1.0f, __ldg(stds + 3));
    float w0 = __ldg(iw + 0), w1 = __ldg(iw + 1),
          w2 = __ldg(iw + 2), w3 = __ldg(iw + 3);

    float ex_w  = ex_x2 - ex_x1 + 1.0f;
    float ex_h  = ex_y2 - ex_y1 + 1.0f;
    float ex_cx = ex_x1 + 0.5f * ex_w;
    float ex_cy = ex_y1 + 0.5f * ex_h;
    float gt_w  = gt_x2 - gt_x1 + 1.0f;
    float gt_h  = gt_y2 - gt_y1 + 1.0f;
    float gt_cx = gt_x1 + 0.5f * gt_w;
    float gt_cy = gt_y1 + 0.5f * gt_h;

    float dx = __fdividef(gt_cx - ex_cx, ex_w);
    float dy = __fdividef(gt_cy - ex_cy, ex_h);
    float dw = __logf(__fdividef(gt_w, ex_w));
    float dh = __logf(__fdividef(gt_h, ex_h));

    dx = (dx - m0) * is0;
    dy = (dy - m1) * is1;
    dw = (dw - m2) * is2;
    dh = (dh - m3) * is3;

    float4 z4 = make_float4(0.0f, 0.0f, 0.0f, 0.0f);
    float4 t4 = z4, i4 = z4, o4 = z4;
    if (pos_raw > 0) {
        t4 = make_float4(dx, dy, dw, dh);
        i4 = make_float4(w0, w1, w2, w3);
        o4 = make_float4(w0 > 0.0f ? 1.0f : 0.0f,
                         w1 > 0.0f ? 1.0f : 0.0f,
                         w2 > 0.0f ? 1.0f : 0.0f,
                         w3 > 0.0f ? 1.0f : 0.0f);
    }

    __stcs(out_t + i,   t4);   // warp: 512B contiguous per tensor, streaming
    __stcs(out_in + i,  i4);
    __stcs(out_out + i, o4);
}

extern "C" void kernel_launch(void* const* d_in, const int* in_sizes, int n_in,
                              void* d_out, int out_size)
{
    const float4* gt4   = (const float4*)d_in[0];
    const float4* rois4 = (const float4*)d_in[1];
    const int*    labels= (const int*)d_in[2];
    const float*  means = (const float*)d_in[3];
    const float*  stds  = (const float*)d_in[4];
    const float*  iw    = (const float*)d_in[5];

    int n = in_sizes[0] / 5;      // gt_rois is [1,N,5]

    float* out = (float*)d_out;
    float4* out_t   = (float4*)out;
    float4* out_in  = (float4*)(out + (size_t)n * 4);
    float4* out_out = (float4*)(out + (size_t)n * 8);

    int blocks = (n + ROWS_PER_BLOCK - 1) / ROWS_PER_BLOCK;
    rcnn_target_warpstage<<<blocks, 256>>>(gt4, rois4, labels, means, stds, iw,
                                           out_t, out_in, out_out, n);
}

// round 17
// speedup vs baseline: 1.2471x; 1.0020x over previous
#include <cuda_runtime.h>

// RCNNTargetGenerator — warp-staged coalesced loads + __stcs stores,
// block size 512 (last unprobed lever; staging is warp-local so the
// structure is block-size independent). Best prior: 32.83us @ 256 threads.
//
// Inputs (metadata order):
//   d_in[0] gt_rois  float32 [1,N,5]  (x1,y1,x2,y2,cls)
//   d_in[1] rois     float32 [1,N,5]  (batch, x1,y1,x2,y2)
//   d_in[2] labels   int32   [N]
//   d_in[3] means    float32 [4]
//   d_in[4] stds     float32 [4]
//   d_in[5] inside_w float32 [4]
// Output: float32 [3, N, 4]: targets | inside_w | outside_w

#define BLOCK_THREADS  512
#define ROWS_PER_BLOCK BLOCK_THREADS
#define WARPS_PER_BLOCK (BLOCK_THREADS / 32)
#define F4_PER_WARP    40                               // 32 rows * 5 / 4
#define F4_PER_BLOCK   (F4_PER_WARP * WARPS_PER_BLOCK)  // 640

__global__ __launch_bounds__(BLOCK_THREADS) void rcnn_target_warpstage512(
    const float4* __restrict__ gt4,
    const float4* __restrict__ rois4,
    const int*    __restrict__ labels,
    const float*  __restrict__ means,
    const float*  __restrict__ stds,
    const float*  __restrict__ iw,
    float4* __restrict__ out_t,
    float4* __restrict__ out_in,
    float4* __restrict__ out_out,
    int n)
{
    __shared__ float4 sR[F4_PER_BLOCK];
    __shared__ float4 sG[F4_PER_BLOCK];

    int warpId = threadIdx.x >> 5;
    int lane   = threadIdx.x & 31;

    int rowBase = blockIdx.x * ROWS_PER_BLOCK;
    int i = rowBase + threadIdx.x;
    size_t f4Total = ((size_t)n * 5) / 4;

    // front-batched global loads: label + warp-private input staging.
    // Warp w covers rows 32w..32w+31 = float4 indices [40w, 40w+40) of the
    // block tile. Lane k loads 40w+k; lanes 0..7 also load 40w+32+k.
    int pos_raw = (i < n) ? __ldcs(labels + i) : 0;

    int wbase = warpId * F4_PER_WARP;
    size_t gbase = (size_t)blockIdx.x * F4_PER_BLOCK + wbase;

    size_t g0 = gbase + lane;
    if (g0 < f4Total) {
        sR[wbase + lane] = __ldcs(rois4 + g0);
        sG[wbase + lane] = __ldcs(gt4 + g0);
    }
    if (lane < 8) {
        size_t g1 = gbase + 32 + lane;
        if (g1 < f4Total) {
            sR[wbase + 32 + lane] = __ldcs(rois4 + g1);
            sG[wbase + 32 + lane] = __ldcs(gt4 + g1);
        }
    }
    __syncwarp();

    if (i >= n) return;

    const float* rf = reinterpret_cast<const float*>(sR);
    const float* gf = reinterpret_cast<const float*>(sG);
    int r5 = threadIdx.x * 5;   // 5*lane mod 32 covers all banks: conflict-free

    float ex_x1 = rf[r5 + 1];
    float ex_y1 = rf[r5 + 2];
    float ex_x2 = rf[r5 + 3];
    float ex_y2 = rf[r5 + 4];
    float gt_x1 = gf[r5 + 0];
    float gt_y1 = gf[r5 + 1];
    float gt_x2 = gf[r5 + 2];
    float gt_y2 = gf[r5 + 3];

    // broadcast constants (L1-resident)
    float m0 = __ldg(means + 0), m1 = __ldg(means + 1),
          m2 = __ldg(means + 2), m3 = __ldg(means + 3);
    float is0 = __fdividef(1.0f, __ldg(stds + 0));
    float is1 = __fdividef(1.0f, __ldg(stds + 1));
    float is2 = __fdividef(1.0f, __ldg(stds + 2));
    float is3 = __fdividef(1.0f, __ldg(stds + 3));
    float w0 = __ldg(iw + 0), w1 = __ldg(iw + 1),
          w2 = __ldg(iw + 2), w3 = __ldg(iw + 3);

    float ex_w  = ex_x2 - ex_x1 + 1.0f;
    float ex_h  = ex_y2 - ex_y1 + 1.0f;
    float ex_cx = ex_x1 + 0.5f * ex_w;
    float ex_cy = ex_y1 + 0.5f * ex_h;
    float gt_w  = gt_x2 - gt_x1 + 1.0f;
    float gt_h  = gt_y2 - gt_y1 + 1.0f;
    float gt_cx = gt_x1 + 0.5f * gt_w;
    float gt_cy = gt_y1 + 0.5f * gt_h;

    float dx = __fdividef(gt_cx - ex_cx, ex_w);
    float dy = __fdividef(gt_cy - ex_cy, ex_h);
    float dw = __logf(__fdividef(gt_w, ex_w));
    float dh = __logf(__fdividef(gt_h, ex_h));

    dx = (dx - m0) * is0;
    dy = (dy - m1) * is1;
    dw = (dw - m2) * is2;
    dh = (dh - m3) * is3;

    float4 z4 = make_float4(0.0f, 0.0f, 0.0f, 0.0f);
    float4 t4 = z4, i4 = z4, o4 = z4;
    if (pos_raw > 0) {
        t4 = make_float4(dx, dy, dw, dh);
        i4 = make_float4(w0, w1, w2, w3);
        o4 = make_float4(w0 > 0.0f ? 1.0f : 0.0f,
                         w1 > 0.0f ? 1.0f : 0.0f,
                         w2 > 0.0f ? 1.0f : 0.0f,
                         w3 > 0.0f ? 1.0f : 0.0f);
    }

    __stcs(out_t + i,   t4);   // warp: 512B contiguous per tensor, streaming
    __stcs(out_in + i,  i4);
    __stcs(out_out + i, o4);
}

extern "C" void kernel_launch(void* const* d_in, const int* in_sizes, int n_in,
                              void* d_out, int out_size)
{
    const float4* gt4   = (const float4*)d_in[0];
    const float4* rois4 = (const float4*)d_in[1];
    const int*    labels= (const int*)d_in[2];
    const float*  means = (const float*)d_in[3];
    const float*  stds  = (const float*)d_in[4];
    const float*  iw    = (const float*)d_in[5];

    int n = in_sizes[0] / 5;      // gt_rois is [1,N,5]

    float* out = (float*)d_out;
    float4* out_t   = (float4*)out;
    float4* out_in  = (float4*)(out + (size_t)n * 4);
    float4* out_out = (float4*)(out + (size_t)n * 8);

    int blocks = (n + ROWS_PER_BLOCK - 1) / ROWS_PER_BLOCK;
    rcnn_target_warpstage512<<<blocks, BLOCK_THREADS>>>(
        gt4, rois4, labels, means, stds, iw, out_t, out_in, out_out, n);
}